// round 4
// baseline (speedup 1.0000x reference)
#include <cuda_runtime.h>
#include <math.h>

// ---------------------------------------------------------------------------
// MAPHead: probe-attention pooling + MLP block.
// Shapes: N=32, L=4096, D=768, H=12, DH=64, MLP=3072. Output [32,768] f32.
//
// Key reduction: q = (probe@wq + bq)/8 is batch-independent (single query).
//   logits[n,h,l] = x[n,l,:] . wkq[:,h] + cb[h],  wkq[d,h] = sum_e wk[d,h,e] q[h,e]
//   xbar[n,h,:]   = sum_l softmax(logits)[l] * x[n,l,:]
//   o[n,h,:]      = xbar[n,h,:] @ wv[:,h,:] + bv[h,:]
//   xa[n,:]       = sum_h o[n,h,:] @ wo[h,:,:] + bo
//   out           = xa + MLP(LN(xa))
// x is streamed exactly once (fused online-softmax pass).
// ---------------------------------------------------------------------------

#define NB   32      // batch
#define LSEQ 4096    // sequence
#define DM   768     // model dim
#define NH   12      // heads
#define DH   64      // head dim
#define MLPD 3072    // mlp dim

#define NCHUNK 32              // L-chunks per batch
#define CROWS  (LSEQ/NCHUNK)   // 128 rows per chunk
#define TR     16              // rows per smem tile
#define NTILE  (CROWS/TR)      // 8 tiles per chunk

#define XPAD   772             // padded row stride in smem (768 + 4) to dodge bank conflicts

// ------------------------------ scratch (device globals) -------------------
__device__ float g_qvec[NH*DH];
__device__ float g_wkq[NH*DM];                 // [h][d]
__device__ float g_cb[NH];
__device__ float g_ms[NB*NCHUNK*NH*2];         // per-(n,chunk,h): m, s
__device__ float g_acc[NB*NCHUNK*NH*DM];       // per-(n,chunk,h): unnormalized xbar (37.7MB)
__device__ float g_xbar[NB*NH*DM];
__device__ float g_xa[NB*DM];
__device__ float g_h1[NB*MLPD];

// ------------------------------ prep 1: qvec --------------------------------
// qvec[h,e] = (probe . wq[:,h,e] + bq[h,e]) / 8
__global__ void prep_qvec(const float* __restrict__ probe,
                          const float* __restrict__ wq,
                          const float* __restrict__ bq) {
    __shared__ float ps[DM];
    int t = threadIdx.x;
    int h = blockIdx.x;
    for (int i = t; i < DM; i += 256) ps[i] = probe[i];
    __syncthreads();
    if (t < DH) {
        int e = t;
        float acc = 0.f;
        const float* w = wq + h*DH + e;
        #pragma unroll 4
        for (int d = 0; d < DM; ++d) acc = fmaf(ps[d], w[(size_t)d*(NH*DH)], acc);
        g_qvec[h*DH + e] = (acc + bq[h*DH + e]) * 0.125f;
    }
}

// ------------------------------ prep 2: wkq, cb -----------------------------
__global__ void prep_wkq(const float* __restrict__ wk,
                         const float* __restrict__ bk) {
    int idx = blockIdx.x*256 + threadIdx.x;      // 0..9215
    if (idx < NH*DM) {
        int d = idx / NH;
        int h = idx - d*NH;
        float acc = 0.f;
        const float* w = wk + (size_t)d*(NH*DH) + h*DH;
        const float* q = g_qvec + h*DH;
        #pragma unroll 8
        for (int e = 0; e < DH; ++e) acc = fmaf(w[e], q[e], acc);
        g_wkq[h*DM + d] = acc;
    }
    if (blockIdx.x == 0 && threadIdx.x < NH) {
        int h = threadIdx.x;
        float acc = 0.f;
        const float* q = g_qvec + h*DH;
        for (int e = 0; e < DH; ++e) acc = fmaf(bk[h*DH + e], q[e], acc);
        g_cb[h] = acc;
    }
}

// ------------------------------ main fused pass -----------------------------
// grid (NCHUNK, NB), block 256. One CTA handles 128 rows of one batch with
// online softmax, producing unnormalized xbar partials + (m,s).
// smem layout (floats):
//   x_s   [TR][XPAD]      12352
//   wk_s  [NH][XPAD]       9264
//   logit [TR*NH]           192
//   p     [TR*NH]           192   (16B aligned, rows of 12)
//   scale [NH], m[NH], s[NH], cb[NH]
#define SM_X    0
#define SM_WK   (SM_X + TR*XPAD)
#define SM_LG   (SM_WK + NH*XPAD)
#define SM_P    (SM_LG + TR*NH)
#define SM_SC   (SM_P + TR*NH)
#define SM_M    (SM_SC + NH)
#define SM_S    (SM_M + NH)
#define SM_CB   (SM_S + NH)
#define SM_TOT  (SM_CB + NH)            // 22048 floats = 88192 B

extern "C" __global__ void __launch_bounds__(256, 2)
map_main(const float* __restrict__ x) {
    extern __shared__ float sm[];
    const int t     = threadIdx.x;
    const int chunk = blockIdx.x;
    const int n     = blockIdx.y;

    // load wkq tile + constants
    {
        const float4* src = (const float4*)g_wkq;
        for (int i = 0; i < 9; ++i) {
            int fi = i*256 + t;
            if (fi < NH*(DM/4)) {
                int h  = fi / (DM/4);
                int c4 = fi - h*(DM/4);
                ((float4*)(sm + SM_WK + h*XPAD))[c4] = src[h*(DM/4) + c4];
            }
        }
        if (t < NH) {
            sm[SM_CB + t] = g_cb[t];
            sm[SM_M  + t] = -1e30f;
            sm[SM_S  + t] = 0.f;
        }
    }

    float acc[NH][3];
    #pragma unroll
    for (int h = 0; h < NH; ++h) { acc[h][0]=0.f; acc[h][1]=0.f; acc[h][2]=0.f; }

    const size_t xbase = ((size_t)n*LSEQ + (size_t)chunk*CROWS) * DM;

    const int ra = t / NH;          // phase-A row (0..15) for t<192
    const int ha = t - ra*NH;       // phase-A head

    __syncthreads();

    for (int tile = 0; tile < NTILE; ++tile) {
        // ---- load 16x768 tile ----
        const float4* gx = (const float4*)(x + xbase + (size_t)tile*TR*DM);
        #pragma unroll
        for (int i = 0; i < 12; ++i) {
            int fi = i*256 + t;                  // 0..3071
            int r  = fi / (DM/4);
            int c4 = fi - r*(DM/4);
            ((float4*)(sm + SM_X + r*XPAD))[c4] = gx[r*(DM/4) + c4];
        }
        __syncthreads();

        // ---- phase A: full-dot logits, thread (r,h) ----
        if (t < TR*NH) {
            const float4* xr = (const float4*)(sm + SM_X  + ra*XPAD);
            const float4* wr = (const float4*)(sm + SM_WK + ha*XPAD);
            float s0=0.f, s1=0.f, s2=0.f, s3=0.f;
            #pragma unroll 8
            for (int i = 0; i < DM/4; ++i) {
                float4 xv = xr[i], wv = wr[i];
                s0 = fmaf(xv.x, wv.x, s0);
                s1 = fmaf(xv.y, wv.y, s1);
                s2 = fmaf(xv.z, wv.z, s2);
                s3 = fmaf(xv.w, wv.w, s3);
            }
            sm[SM_LG + t] = (s0+s1) + (s2+s3) + sm[SM_CB + ha];
        }
        __syncthreads();

        // ---- online softmax state update (12 threads) ----
        if (t < NH) {
            float mo = sm[SM_M + t], so = sm[SM_S + t];
            float nm = mo;
            #pragma unroll
            for (int r = 0; r < TR; ++r) nm = fmaxf(nm, sm[SM_LG + r*NH + t]);
            float sc = __expf(mo - nm);
            float ss = so * sc;
            #pragma unroll
            for (int r = 0; r < TR; ++r) {
                float e = __expf(sm[SM_LG + r*NH + t] - nm);
                sm[SM_P + r*NH + t] = e;
                ss += e;
            }
            sm[SM_M + t] = nm;
            sm[SM_S + t] = ss;
            sm[SM_SC + t] = sc;
        }
        __syncthreads();

        // ---- phase B: rescale + rank-16 accumulation, col-distributed ----
        #pragma unroll
        for (int h = 0; h < NH; ++h) {
            float sc = sm[SM_SC + h];
            acc[h][0] *= sc; acc[h][1] *= sc; acc[h][2] *= sc;
        }
        #pragma unroll 2
        for (int r = 0; r < TR; ++r) {
            float x0 = sm[SM_X + r*XPAD + t];
            float x1 = sm[SM_X + r*XPAD + t + 256];
            float x2 = sm[SM_X + r*XPAD + t + 512];
            const float4* pp = (const float4*)(sm + SM_P + r*NH);
            float4 pA = pp[0], pB = pp[1], pC = pp[2];
            float pv[NH] = {pA.x,pA.y,pA.z,pA.w, pB.x,pB.y,pB.z,pB.w, pC.x,pC.y,pC.z,pC.w};
            #pragma unroll
            for (int h = 0; h < NH; ++h) {
                acc[h][0] = fmaf(pv[h], x0, acc[h][0]);
                acc[h][1] = fmaf(pv[h], x1, acc[h][1]);
                acc[h][2] = fmaf(pv[h], x2, acc[h][2]);
            }
        }
        __syncthreads();   // before next tile overwrites x_s
    }

    // ---- write partials ----
    #pragma unroll
    for (int h = 0; h < NH; ++h) {
        float* dst = g_acc + (((size_t)(n*NCHUNK + chunk)*NH + h) * DM);
        dst[t]       = acc[h][0];
        dst[t + 256] = acc[h][1];
        dst[t + 512] = acc[h][2];
    }
    if (t < NH) {
        size_t mi = ((size_t)(n*NCHUNK + chunk)*NH + t) * 2;
        g_ms[mi]   = sm[SM_M + t];
        g_ms[mi+1] = sm[SM_S + t];
    }
}

// ------------------------------ merge partials ------------------------------
// grid (NH, NB), block 256 -> g_xbar[n][h][d]
__global__ void map_merge1() {
    int h = blockIdx.x, n = blockIdx.y, t = threadIdx.x;
    float M = -1e30f;
    #pragma unroll 4
    for (int c = 0; c < NCHUNK; ++c)
        M = fmaxf(M, g_ms[((size_t)(n*NCHUNK + c)*NH + h)*2]);
    float S = 0.f;
    #pragma unroll 4
    for (int c = 0; c < NCHUNK; ++c) {
        size_t mi = ((size_t)(n*NCHUNK + c)*NH + h)*2;
        S += __expf(g_ms[mi] - M) * g_ms[mi+1];
    }
    float inv = 1.f / S;
    float v0=0.f, v1=0.f, v2=0.f;
    for (int c = 0; c < NCHUNK; ++c) {
        size_t mi = ((size_t)(n*NCHUNK + c)*NH + h)*2;
        float w = __expf(g_ms[mi] - M);
        const float* ap = g_acc + ((size_t)(n*NCHUNK + c)*NH + h)*DM;
        v0 = fmaf(w, ap[t],       v0);
        v1 = fmaf(w, ap[t + 256], v1);
        v2 = fmaf(w, ap[t + 512], v2);
    }
    float* xb = g_xbar + ((size_t)n*NH + h)*DM;
    xb[t]       = v0 * inv;
    xb[t + 256] = v1 * inv;
    xb[t + 512] = v2 * inv;
}

// ------------------------------ o = xbar@wv+bv ; xa = o@wo+bo ---------------
// grid (NB), block 256
__global__ void map_proj(const float* __restrict__ wv, const float* __restrict__ bv,
                         const float* __restrict__ wo, const float* __restrict__ bo) {
    __shared__ float xb[NH*DM];
    __shared__ float o_s[NH*DH];
    int n = blockIdx.x, t = threadIdx.x;
    for (int i = 0; i < NH*DM/256; ++i) xb[i*256 + t] = g_xbar[(size_t)n*NH*DM + i*256 + t];
    __syncthreads();
    #pragma unroll
    for (int j = 0; j < 3; ++j) {
        int he = j*256 + t;                      // h*64+e
        int h = he >> 6;
        float a = bv[he];
        const float* xh = xb + h*DM;
        #pragma unroll 4
        for (int d = 0; d < DM; ++d) a = fmaf(xh[d], wv[(size_t)d*(NH*DH) + he], a);
        o_s[he] = a;
    }
    __syncthreads();
    #pragma unroll
    for (int j = 0; j < 3; ++j) {
        int d = j*256 + t;
        float a = bo[d];
        #pragma unroll 4
        for (int he = 0; he < NH*DH; ++he) a = fmaf(o_s[he], wo[(size_t)he*DM + d], a);
        g_xa[(size_t)n*DM + d] = a;
    }
}

// ------------------------------ MLP stage 1: LN + gelu(y@w1+b1) -------------
// grid (12, NB), block 256
__global__ void map_mlp1(const float* __restrict__ ln_s, const float* __restrict__ ln_b,
                         const float* __restrict__ w1,   const float* __restrict__ b1) {
    __shared__ float xa_s[DM];
    __shared__ float y_s[DM];
    __shared__ float red[256];
    int n = blockIdx.y, bj = blockIdx.x, t = threadIdx.x;
    for (int j = 0; j < 3; ++j) xa_s[j*256 + t] = g_xa[(size_t)n*DM + j*256 + t];
    __syncthreads();
    // mean
    red[t] = xa_s[t] + xa_s[t+256] + xa_s[t+512];
    __syncthreads();
    for (int s = 128; s > 0; s >>= 1) { if (t < s) red[t] += red[t+s]; __syncthreads(); }
    float mu = red[0] * (1.f/DM);
    __syncthreads();
    // var
    {
        float d0 = xa_s[t]-mu, d1 = xa_s[t+256]-mu, d2 = xa_s[t+512]-mu;
        red[t] = d0*d0 + d1*d1 + d2*d2;
    }
    __syncthreads();
    for (int s = 128; s > 0; s >>= 1) { if (t < s) red[t] += red[t+s]; __syncthreads(); }
    float rstd = rsqrtf(red[0] * (1.f/DM) + 1e-6f);
    __syncthreads();
    for (int j = 0; j < 3; ++j) {
        int d = j*256 + t;
        y_s[d] = (xa_s[d] - mu) * rstd * ln_s[d] + ln_b[d];
    }
    __syncthreads();
    int k = bj*256 + t;
    float a = b1[k];
    #pragma unroll 4
    for (int d = 0; d < DM; ++d) a = fmaf(y_s[d], w1[(size_t)d*MLPD + k], a);
    // gelu (tanh approximation, matches jax.nn.gelu default)
    float u = 0.7978845608028654f * (a + 0.044715f * a * a * a);
    g_h1[(size_t)n*MLPD + k] = 0.5f * a * (1.f + tanhf(u));
}

// ------------------------------ MLP stage 2: out = xa + h1@w2 + b2 ----------
// grid (3, NB), block 256
__global__ void map_mlp2(const float* __restrict__ w2, const float* __restrict__ b2,
                         float* __restrict__ out) {
    __shared__ float h1_s[MLPD];
    int n = blockIdx.y, bj = blockIdx.x, t = threadIdx.x;
    for (int i = 0; i < MLPD/256; ++i) h1_s[i*256 + t] = g_h1[(size_t)n*MLPD + i*256 + t];
    __syncthreads();
    int d = bj*256 + t;
    float a = b2[d];
    #pragma unroll 4
    for (int k = 0; k < MLPD; ++k) a = fmaf(h1_s[k], w2[(size_t)k*DM + d], a);
    out[(size_t)n*DM + d] = g_xa[(size_t)n*DM + d] + a;
}

// ------------------------------ launcher ------------------------------------
extern "C" void kernel_launch(void* const* d_in, const int* in_sizes, int n_in,
                              void* d_out, int out_size) {
    const float* x     = (const float*)d_in[0];
    const float* probe = (const float*)d_in[1];
    const float* wq    = (const float*)d_in[2];
    const float* bq    = (const float*)d_in[3];
    const float* wk    = (const float*)d_in[4];
    const float* bk    = (const float*)d_in[5];
    const float* wv    = (const float*)d_in[6];
    const float* bv    = (const float*)d_in[7];
    const float* wo    = (const float*)d_in[8];
    const float* bo    = (const float*)d_in[9];
    const float* ln_s  = (const float*)d_in[10];
    const float* ln_b  = (const float*)d_in[11];
    const float* w1    = (const float*)d_in[12];
    const float* b1    = (const float*)d_in[13];
    const float* w2    = (const float*)d_in[14];
    const float* b2    = (const float*)d_in[15];
    float* out = (float*)d_out;

    const int smem_main = SM_TOT * (int)sizeof(float);   // 88192 B
    cudaFuncSetAttribute(map_main, cudaFuncAttributeMaxDynamicSharedMemorySize, smem_main);

    prep_qvec<<<NH, 256>>>(probe, wq, bq);
    prep_wkq<<<(NH*DM + 255)/256, 256>>>(wk, bk);
    map_main<<<dim3(NCHUNK, NB), 256, smem_main>>>(x);
    map_merge1<<<dim3(NH, NB), 256>>>();
    map_proj<<<NB, 256>>>(wv, bv, wo, bo);
    map_mlp1<<<dim3(MLPD/256, NB), 256>>>(ln_s, ln_b, w1, b1);
    map_mlp2<<<dim3(DM/256, NB), 256>>>(w2, b2, out);
}